// round 4
// baseline (speedup 1.0000x reference)
#include <cuda_runtime.h>

#ifndef B_DIM
#define B_DIM 8
#define N_DIM 8192
#define M_DIM 128
#endif

constexpr int WARPS_PER_CTA = 8;
constexpr int PTS_PER_WARP  = 8;
constexpr int PTS_PER_CTA   = WARPS_PER_CTA * PTS_PER_WARP;  // 64
constexpr int THREADS       = WARPS_PER_CTA * 32;            // 256

typedef unsigned long long u64;

// ---------- packed f32x2 helpers (Blackwell) ----------
__device__ __forceinline__ u64 pack2(float lo, float hi) {
    u64 r; asm("mov.b64 %0, {%1,%2};" : "=l"(r) : "f"(lo), "f"(hi)); return r;
}
__device__ __forceinline__ u64 splat2(float v) { return pack2(v, v); }
__device__ __forceinline__ void unpack2(u64 v, float& lo, float& hi) {
    asm("mov.b64 {%0,%1}, %2;" : "=f"(lo), "=f"(hi) : "l"(v));
}
__device__ __forceinline__ u64 fma2(u64 a, u64 b, u64 c) {
    u64 d; asm("fma.rn.f32x2 %0, %1, %2, %3;" : "=l"(d) : "l"(a), "l"(b), "l"(c)); return d;
}
__device__ __forceinline__ u64 mul2(u64 a, u64 b) {
    u64 d; asm("mul.rn.f32x2 %0, %1, %2;" : "=l"(d) : "l"(a), "l"(b)); return d;
}
__device__ __forceinline__ u64 add2(u64 a, u64 b) {
    u64 d; asm("add.rn.f32x2 %0, %1, %2;" : "=l"(d) : "l"(a), "l"(b)); return d;
}
__device__ __forceinline__ float sqrt_approx(float x) {
    float r; asm("sqrt.approx.f32 %0, %1;" : "=f"(r) : "f"(x)); return r;
}
__device__ __forceinline__ float rcp_approx(float x) {
    float r; asm("rcp.approx.f32 %0, %1;" : "=f"(r) : "f"(x)); return r;
}

struct Consts {
    u64 aS[4];        // splat(W1[j][0])
    u64 w2S[4][4];    // splat(W2[j][i])
    u64 b2S[4];
    u64 w3S[4];
    u64 b3S;
    u64 k04, k06;
};

// leaky(x) = max(x, 0.2x) = 0.6x + 0.4|x| — stays packed, no unpack/FMNMX
__device__ __forceinline__ u64 leaky2(u64 z, const Consts& C) {
    const u64 az = z & 0x7FFFFFFF7FFFFFFFULL;           // packed abs (2x LOP)
    return fma2(C.k04, az, mul2(C.k06, z));
}

// MLP for one m-pair: f_pair -> out_pair. All weights are loop-invariant splats.
__device__ __forceinline__ u64 mlp_pair(u64 f, const u64 c[4], const Consts& C) {
    const u64 h0 = leaky2(fma2(C.aS[0], f, c[0]), C);
    const u64 h1 = leaky2(fma2(C.aS[1], f, c[1]), C);
    const u64 h2 = leaky2(fma2(C.aS[2], f, c[2]), C);
    const u64 h3 = leaky2(fma2(C.aS[3], f, c[3]), C);
    const u64 g0 = leaky2(fma2(C.w2S[0][0], h0, fma2(C.w2S[0][1], h1,
                          fma2(C.w2S[0][2], h2, fma2(C.w2S[0][3], h3, C.b2S[0])))), C);
    const u64 g1 = leaky2(fma2(C.w2S[1][0], h0, fma2(C.w2S[1][1], h1,
                          fma2(C.w2S[1][2], h2, fma2(C.w2S[1][3], h3, C.b2S[1])))), C);
    const u64 g2 = leaky2(fma2(C.w2S[2][0], h0, fma2(C.w2S[2][1], h1,
                          fma2(C.w2S[2][2], h2, fma2(C.w2S[2][3], h3, C.b2S[2])))), C);
    const u64 g3 = leaky2(fma2(C.w2S[3][0], h0, fma2(C.w2S[3][1], h1,
                          fma2(C.w2S[3][2], h2, fma2(C.w2S[3][3], h3, C.b2S[3])))), C);
    return fma2(C.w3S[0], g0, fma2(C.w3S[1], g1,
           fma2(C.w3S[2], g2, fma2(C.w3S[3], g3, C.b3S))));
}

__global__ void __launch_bounds__(THREADS)
featuration_kernel(const float* __restrict__ xyz,   // [B,3,N]
                   const float* __restrict__ V,     // [B,M,3]
                   const float* __restrict__ W1,    // [4,4]
                   const float* __restrict__ b1,    // [4]
                   const float* __restrict__ W2,    // [4,4]
                   const float* __restrict__ b2,    // [4]
                   const float* __restrict__ W3,    // [1,4]
                   const float* __restrict__ b3,    // [1]
                   float* __restrict__ out)         // [B,N,M]
{
    __shared__ float4 Vs[M_DIM];   // (Vx,Vy,Vz,0) per m
    __shared__ float4 Cs[M_DIM];   // hoisted layer-1 constants per m

    const int b   = blockIdx.y;
    const int tid = threadIdx.x;

    if (tid < M_DIM) {
        const float vx = __ldg(&V[(b * M_DIM + tid) * 3 + 0]);
        const float vy = __ldg(&V[(b * M_DIM + tid) * 3 + 1]);
        const float vz = __ldg(&V[(b * M_DIM + tid) * 3 + 2]);
        Vs[tid] = make_float4(vx, vy, vz, 0.0f);
        float4 c;
        c.x = fmaf(__ldg(&W1[1]),  vx, fmaf(__ldg(&W1[2]),  vy, fmaf(__ldg(&W1[3]),  vz, __ldg(&b1[0]))));
        c.y = fmaf(__ldg(&W1[5]),  vx, fmaf(__ldg(&W1[6]),  vy, fmaf(__ldg(&W1[7]),  vz, __ldg(&b1[1]))));
        c.z = fmaf(__ldg(&W1[9]),  vx, fmaf(__ldg(&W1[10]), vy, fmaf(__ldg(&W1[11]), vz, __ldg(&b1[2]))));
        c.w = fmaf(__ldg(&W1[13]), vx, fmaf(__ldg(&W1[14]), vy, fmaf(__ldg(&W1[15]), vz, __ldg(&b1[3]))));
        Cs[tid] = c;
    }

    // ---- loop-invariant splat constants ----
    Consts C;
#pragma unroll
    for (int j = 0; j < 4; j++) {
        C.aS[j]  = splat2(__ldg(&W1[4 * j]));
#pragma unroll
        for (int i = 0; i < 4; i++) C.w2S[j][i] = splat2(__ldg(&W2[4 * j + i]));
        C.b2S[j] = splat2(__ldg(&b2[j]));
        C.w3S[j] = splat2(__ldg(&W3[j]));
    }
    C.b3S = splat2(__ldg(&b3[0]));
    C.k04 = splat2(0.4f);
    C.k06 = splat2(0.6f);

    __syncthreads();

    const int warp = tid >> 5;
    const int lane = tid & 31;

    // lane owns m = 4l..4l+3 as pairs A=(4l,4l+1), B=(4l+2,4l+3)
    const float4 v0 = Vs[4 * lane + 0];
    const float4 v1 = Vs[4 * lane + 1];
    const float4 v2 = Vs[4 * lane + 2];
    const float4 v3 = Vs[4 * lane + 3];
    const u64 nvxA = pack2(-v0.x, -v1.x), nvyA = pack2(-v0.y, -v1.y), nvzA = pack2(-v0.z, -v1.z);
    const u64 nvxB = pack2(-v2.x, -v3.x), nvyB = pack2(-v2.y, -v3.y), nvzB = pack2(-v2.z, -v3.z);

    // layer-1 constants packed across the m-pair (per hidden unit j)
    const float4 cc0 = Cs[4 * lane + 0];
    const float4 cc1 = Cs[4 * lane + 1];
    const float4 cc2 = Cs[4 * lane + 2];
    const float4 cc3 = Cs[4 * lane + 3];
    u64 cA[4], cB[4];
    cA[0] = pack2(cc0.x, cc1.x); cA[1] = pack2(cc0.y, cc1.y);
    cA[2] = pack2(cc0.z, cc1.z); cA[3] = pack2(cc0.w, cc1.w);
    cB[0] = pack2(cc2.x, cc3.x); cB[1] = pack2(cc2.y, cc3.y);
    cB[2] = pack2(cc2.z, cc3.z); cB[3] = pack2(cc2.w, cc3.w);

    const float* xb = xyz + (size_t)b * 3 * N_DIM;
    float* outb = out + (size_t)b * N_DIM * M_DIM;

    const int n_base = blockIdx.x * PTS_PER_CTA + warp * PTS_PER_WARP;

#pragma unroll
    for (int p = 0; p < PTS_PER_WARP; p++) {
        const int n = n_base + p;
        const float px = __ldg(&xb[n]);
        const float py = __ldg(&xb[N_DIM + n]);
        const float pz = __ldg(&xb[2 * N_DIM + n]);
        const u64 pxs = splat2(px), pys = splat2(py), pzs = splat2(pz);

        // squared distances, packed across m-pairs
        const u64 dxA = add2(pxs, nvxA), dyA = add2(pys, nvyA), dzA = add2(pzs, nvzA);
        const u64 sA  = fma2(dxA, dxA, fma2(dyA, dyA, mul2(dzA, dzA)));
        const u64 dxB = add2(pxs, nvxB), dyB = add2(pys, nvyB), dzB = add2(pzs, nvzB);
        const u64 sB  = fma2(dxB, dxB, fma2(dyB, dyB, mul2(dzB, dzB)));

        float s0, s1, s2, s3;
        unpack2(sA, s0, s1); unpack2(sB, s2, s3);
        const float d0 = sqrt_approx(s0);
        const float d1 = sqrt_approx(s1);
        const float d2 = sqrt_approx(s2);
        const float d3 = sqrt_approx(s3);

        // warp-wide min/max over all 128 m
        float mn = fminf(fminf(d0, d1), fminf(d2, d3));
        float mx = fmaxf(fmaxf(d0, d1), fmaxf(d2, d3));
#pragma unroll
        for (int off = 16; off > 0; off >>= 1) {
            mn = fminf(mn, __shfl_xor_sync(0xFFFFFFFFu, mn, off));
            mx = fmaxf(mx, __shfl_xor_sync(0xFFFFFFFFu, mx, off));
        }
        const float denom = mx - mn;
        const float inv = (denom > 0.0f) ? rcp_approx(denom) : 0.0f;
        const float nmninv = -mn * inv;
        const u64 invS = splat2(inv), nmS = splat2(nmninv);

        const u64 dA = pack2(d0, d1), dB = pack2(d2, d3);
        const u64 fA = fma2(dA, invS, nmS);
        const u64 fB = fma2(dB, invS, nmS);

        const u64 oA = mlp_pair(fA, cA, C);
        const u64 oB = mlp_pair(fB, cB, C);

        // coalesced 16B store: (m, m+1, m+2, m+3)
        reinterpret_cast<ulonglong2*>(outb + (size_t)n * M_DIM)[lane] =
            make_ulonglong2(oA, oB);
    }
}

extern "C" void kernel_launch(void* const* d_in, const int* in_sizes, int n_in,
                              void* d_out, int out_size) {
    const float* xyz = (const float*)d_in[0];
    const float* V   = (const float*)d_in[1];
    const float* W1  = (const float*)d_in[2];
    const float* b1  = (const float*)d_in[3];
    const float* W2  = (const float*)d_in[4];
    const float* b2  = (const float*)d_in[5];
    const float* W3  = (const float*)d_in[6];
    const float* b3  = (const float*)d_in[7];
    float* out = (float*)d_out;

    dim3 grid(N_DIM / PTS_PER_CTA, B_DIM);  // (128, 8)
    featuration_kernel<<<grid, THREADS>>>(xyz, V, W1, b1, W2, b2, W3, b3, out);
}

// round 5
// speedup vs baseline: 1.0586x; 1.0586x over previous
#include <cuda_runtime.h>

#ifndef B_DIM
#define B_DIM 8
#define N_DIM 8192
#define M_DIM 128
#endif

constexpr int WARPS_PER_CTA = 4;
constexpr int PTS_PER_WARP  = 8;
constexpr int PTS_PER_CTA   = WARPS_PER_CTA * PTS_PER_WARP;  // 32
constexpr int THREADS       = WARPS_PER_CTA * 32;            // 128

typedef unsigned long long u64;

// ---------- packed f32x2 helpers (Blackwell) ----------
__device__ __forceinline__ u64 pack2(float lo, float hi) {
    u64 r; asm("mov.b64 %0, {%1,%2};" : "=l"(r) : "f"(lo), "f"(hi)); return r;
}
__device__ __forceinline__ void unpack2(u64 v, float& lo, float& hi) {
    asm("mov.b64 {%0,%1}, %2;" : "=f"(lo), "=f"(hi) : "l"(v));
}
__device__ __forceinline__ u64 fma2(u64 a, u64 b, u64 c) {
    u64 d; asm("fma.rn.f32x2 %0, %1, %2, %3;" : "=l"(d) : "l"(a), "l"(b), "l"(c)); return d;
}
__device__ __forceinline__ u64 mul2(u64 a, u64 b) {
    u64 d; asm("mul.rn.f32x2 %0, %1, %2;" : "=l"(d) : "l"(a), "l"(b)); return d;
}
__device__ __forceinline__ u64 add2(u64 a, u64 b) {
    u64 d; asm("add.rn.f32x2 %0, %1, %2;" : "=l"(d) : "l"(a), "l"(b)); return d;
}

__device__ __forceinline__ float sqrt_approx(float x) {
    float r; asm("sqrt.approx.f32 %0, %1;" : "=f"(r) : "f"(x)); return r;
}
__device__ __forceinline__ float rcp_approx(float x) {
    float r; asm("rcp.approx.f32 %0, %1;" : "=f"(r) : "f"(x)); return r;
}

// packed leaky: max(z, 0.2z) per component
__device__ __forceinline__ u64 leaky2(u64 z, u64 k02) {
    u64 t = mul2(z, k02);
    float z0, z1, t0, t1;
    unpack2(z, z0, z1); unpack2(t, t0, t1);
    return pack2(fmaxf(z0, t0), fmaxf(z1, t1));
}

struct MlpConsts {
    u64 a01, a23;              // layer-1 f-coeffs packed across hidden pairs
    u64 w2p01[4], w2p23[4];    // w2p01[i] = (W2[0][i], W2[1][i]); w2p23[i] = (W2[2][i], W2[3][i])
    u64 b2p01, b2p23;
    u64 w3p01, w3p23;
    u64 b3p;                   // (b3, 0)
    u64 k02;                   // (0.2, 0.2)
};

// full MLP for one element given f and its per-m layer-1 constants (packed across hidden dim)
__device__ __forceinline__ float mlp_eval(float f, u64 c01, u64 c23, const MlpConsts& C) {
    const u64 fs = pack2(f, f);
    const u64 h01 = leaky2(fma2(C.a01, fs, c01), C.k02);
    const u64 h23 = leaky2(fma2(C.a23, fs, c23), C.k02);
    float h0, h1, h2, h3;
    unpack2(h01, h0, h1); unpack2(h23, h2, h3);
    const u64 h0s = pack2(h0, h0), h1s = pack2(h1, h1),
              h2s = pack2(h2, h2), h3s = pack2(h3, h3);
    u64 z2a = fma2(h0s, C.w2p01[0],
              fma2(h1s, C.w2p01[1],
              fma2(h2s, C.w2p01[2],
              fma2(h3s, C.w2p01[3], C.b2p01))));
    u64 z2b = fma2(h0s, C.w2p23[0],
              fma2(h1s, C.w2p23[1],
              fma2(h2s, C.w2p23[2],
              fma2(h3s, C.w2p23[3], C.b2p23))));
    const u64 g01 = leaky2(z2a, C.k02);
    const u64 g23 = leaky2(z2b, C.k02);
    const u64 acc = fma2(C.w3p01, g01, fma2(C.w3p23, g23, C.b3p));
    float lo, hi; unpack2(acc, lo, hi);
    return lo + hi;
}

__global__ void __launch_bounds__(THREADS)
featuration_kernel(const float* __restrict__ xyz,   // [B,3,N]
                   const float* __restrict__ V,     // [B,M,3]
                   const float* __restrict__ W1,    // [4,4]
                   const float* __restrict__ b1,    // [4]
                   const float* __restrict__ W2,    // [4,4]
                   const float* __restrict__ b2,    // [4]
                   const float* __restrict__ W3,    // [1,4]
                   const float* __restrict__ b3,    // [1]
                   float* __restrict__ out)         // [B,N,M]
{
    __shared__ float4 Vs[M_DIM];   // (Vx,Vy,Vz,0) per m
    __shared__ float4 Cs[M_DIM];   // hoisted layer-1 constants per m

    const int b   = blockIdx.y;
    const int tid = threadIdx.x;

    // ---- per-CTA init: load V for this batch, precompute layer-1 constants ----
    // THREADS == 128 == M_DIM: every thread handles one m
    {
        const float vx = __ldg(&V[(b * M_DIM + tid) * 3 + 0]);
        const float vy = __ldg(&V[(b * M_DIM + tid) * 3 + 1]);
        const float vz = __ldg(&V[(b * M_DIM + tid) * 3 + 2]);
        Vs[tid] = make_float4(vx, vy, vz, 0.0f);
        float4 c;
        c.x = fmaf(__ldg(&W1[1]),  vx, fmaf(__ldg(&W1[2]),  vy, fmaf(__ldg(&W1[3]),  vz, __ldg(&b1[0]))));
        c.y = fmaf(__ldg(&W1[5]),  vx, fmaf(__ldg(&W1[6]),  vy, fmaf(__ldg(&W1[7]),  vz, __ldg(&b1[1]))));
        c.z = fmaf(__ldg(&W1[9]),  vx, fmaf(__ldg(&W1[10]), vy, fmaf(__ldg(&W1[11]), vz, __ldg(&b1[2]))));
        c.w = fmaf(__ldg(&W1[13]), vx, fmaf(__ldg(&W1[14]), vy, fmaf(__ldg(&W1[15]), vz, __ldg(&b1[3]))));
        Cs[tid] = c;
    }

    // ---- global weight constants, packed across the hidden axis ----
    MlpConsts C;
    C.a01 = pack2(__ldg(&W1[0]),  __ldg(&W1[4]));
    C.a23 = pack2(__ldg(&W1[8]),  __ldg(&W1[12]));
#pragma unroll
    for (int i = 0; i < 4; i++) {
        C.w2p01[i] = pack2(__ldg(&W2[i]),     __ldg(&W2[4 + i]));
        C.w2p23[i] = pack2(__ldg(&W2[8 + i]), __ldg(&W2[12 + i]));
    }
    C.b2p01 = pack2(__ldg(&b2[0]), __ldg(&b2[1]));
    C.b2p23 = pack2(__ldg(&b2[2]), __ldg(&b2[3]));
    C.w3p01 = pack2(__ldg(&W3[0]), __ldg(&W3[1]));
    C.w3p23 = pack2(__ldg(&W3[2]), __ldg(&W3[3]));
    C.b3p   = pack2(__ldg(&b3[0]), 0.0f);
    C.k02   = pack2(0.2f, 0.2f);

    __syncthreads();

    const int warp = tid >> 5;
    const int lane = tid & 31;

    // lane owns m = 4*lane .. 4*lane+3 ; negated V packed across m-pairs
    const float4 v0 = Vs[4 * lane + 0];
    const float4 v1 = Vs[4 * lane + 1];
    const float4 v2 = Vs[4 * lane + 2];
    const float4 v3 = Vs[4 * lane + 3];
    const u64 nvxA = pack2(-v0.x, -v1.x), nvyA = pack2(-v0.y, -v1.y), nvzA = pack2(-v0.z, -v1.z);
    const u64 nvxB = pack2(-v2.x, -v3.x), nvyB = pack2(-v2.y, -v3.y), nvzB = pack2(-v2.z, -v3.z);

    // layer-1 constants packed across hidden dim, per owned m
    const float4 cc0 = Cs[4 * lane + 0];
    const float4 cc1 = Cs[4 * lane + 1];
    const float4 cc2 = Cs[4 * lane + 2];
    const float4 cc3 = Cs[4 * lane + 3];
    const u64 c0_01 = pack2(cc0.x, cc0.y), c0_23 = pack2(cc0.z, cc0.w);
    const u64 c1_01 = pack2(cc1.x, cc1.y), c1_23 = pack2(cc1.z, cc1.w);
    const u64 c2_01 = pack2(cc2.x, cc2.y), c2_23 = pack2(cc2.z, cc2.w);
    const u64 c3_01 = pack2(cc3.x, cc3.y), c3_23 = pack2(cc3.z, cc3.w);

    const float* xb = xyz + (size_t)b * 3 * N_DIM;
    float* outb = out + (size_t)b * N_DIM * M_DIM;

    const int n_base = blockIdx.x * PTS_PER_CTA + warp * PTS_PER_WARP;

#pragma unroll
    for (int p = 0; p < PTS_PER_WARP; p++) {
        const int n = n_base + p;
        const float px = __ldg(&xb[n]);
        const float py = __ldg(&xb[N_DIM + n]);
        const float pz = __ldg(&xb[2 * N_DIM + n]);
        const u64 pxs = pack2(px, px), pys = pack2(py, py), pzs = pack2(pz, pz);

        // squared distances, packed across m-pairs
        u64 dxA = add2(pxs, nvxA), dyA = add2(pys, nvyA), dzA = add2(pzs, nvzA);
        u64 sA = fma2(dxA, dxA, fma2(dyA, dyA, mul2(dzA, dzA)));
        u64 dxB = add2(pxs, nvxB), dyB = add2(pys, nvyB), dzB = add2(pzs, nvzB);
        u64 sB = fma2(dxB, dxB, fma2(dyB, dyB, mul2(dzB, dzB)));
        float s0, s1, s2, s3;
        unpack2(sA, s0, s1); unpack2(sB, s2, s3);

        // butterfly on SQUARED distances (sqrt is monotone) so the four
        // per-element MUFU sqrts below overlap the SHFL chain
        float mns = fminf(fminf(s0, s1), fminf(s2, s3));
        float mxs = fmaxf(fmaxf(s0, s1), fmaxf(s2, s3));
#pragma unroll
        for (int off = 16; off > 0; off >>= 1) {
            mns = fminf(mns, __shfl_xor_sync(0xFFFFFFFFu, mns, off));
            mxs = fmaxf(mxs, __shfl_xor_sync(0xFFFFFFFFu, mxs, off));
        }

        const float d0 = sqrt_approx(s0);
        const float d1 = sqrt_approx(s1);
        const float d2 = sqrt_approx(s2);
        const float d3 = sqrt_approx(s3);

        const float mn = sqrt_approx(mns);
        const float mx = sqrt_approx(mxs);
        const float denom = mx - mn;
        const float inv = (denom > 0.0f) ? rcp_approx(denom) : 0.0f;
        const float nmninv = -mn * inv;

        float4 res;
        res.x = mlp_eval(fmaf(d0, inv, nmninv), c0_01, c0_23, C);
        res.y = mlp_eval(fmaf(d1, inv, nmninv), c1_01, c1_23, C);
        res.z = mlp_eval(fmaf(d2, inv, nmninv), c2_01, c2_23, C);
        res.w = mlp_eval(fmaf(d3, inv, nmninv), c3_01, c3_23, C);

        // coalesced: warp writes 128 contiguous floats
        reinterpret_cast<float4*>(outb + (size_t)n * M_DIM)[lane] = res;
    }
}

extern "C" void kernel_launch(void* const* d_in, const int* in_sizes, int n_in,
                              void* d_out, int out_size) {
    const float* xyz = (const float*)d_in[0];
    const float* V   = (const float*)d_in[1];
    const float* W1  = (const float*)d_in[2];
    const float* b1  = (const float*)d_in[3];
    const float* W2  = (const float*)d_in[4];
    const float* b2  = (const float*)d_in[5];
    const float* W3  = (const float*)d_in[6];
    const float* b3  = (const float*)d_in[7];
    float* out = (float*)d_out;

    dim3 grid(N_DIM / PTS_PER_CTA, B_DIM);  // (256, 8)
    featuration_kernel<<<grid, THREADS>>>(xyz, V, W1, b1, W2, b2, W3, b3, out);
}

// round 6
// speedup vs baseline: 1.0615x; 1.0027x over previous
#include <cuda_runtime.h>

#ifndef B_DIM
#define B_DIM 8
#define N_DIM 8192
#define M_DIM 128
#endif

constexpr int WARPS_PER_CTA = 4;
constexpr int PTS_PER_WARP  = 8;
constexpr int PTS_PER_CTA   = WARPS_PER_CTA * PTS_PER_WARP;  // 32
constexpr int THREADS       = WARPS_PER_CTA * 32;            // 128

typedef unsigned long long u64;

// ---------- packed f32x2 helpers (Blackwell) ----------
__device__ __forceinline__ u64 pack2(float lo, float hi) {
    u64 r; asm("mov.b64 %0, {%1,%2};" : "=l"(r) : "f"(lo), "f"(hi)); return r;
}
__device__ __forceinline__ void unpack2(u64 v, float& lo, float& hi) {
    asm("mov.b64 {%0,%1}, %2;" : "=f"(lo), "=f"(hi) : "l"(v));
}
__device__ __forceinline__ u64 fma2(u64 a, u64 b, u64 c) {
    u64 d; asm("fma.rn.f32x2 %0, %1, %2, %3;" : "=l"(d) : "l"(a), "l"(b), "l"(c)); return d;
}
__device__ __forceinline__ u64 mul2(u64 a, u64 b) {
    u64 d; asm("mul.rn.f32x2 %0, %1, %2;" : "=l"(d) : "l"(a), "l"(b)); return d;
}
__device__ __forceinline__ u64 add2(u64 a, u64 b) {
    u64 d; asm("add.rn.f32x2 %0, %1, %2;" : "=l"(d) : "l"(a), "l"(b)); return d;
}

__device__ __forceinline__ float sqrt_approx(float x) {
    float r; asm("sqrt.approx.f32 %0, %1;" : "=f"(r) : "f"(x)); return r;
}
__device__ __forceinline__ float rcp_approx(float x) {
    float r; asm("rcp.approx.f32 %0, %1;" : "=f"(r) : "f"(x)); return r;
}

// packed leaky: max(z, 0.2z) per component
__device__ __forceinline__ u64 leaky2(u64 z, u64 k02) {
    u64 t = mul2(z, k02);
    float z0, z1, t0, t1;
    unpack2(z, z0, z1); unpack2(t, t0, t1);
    return pack2(fmaxf(z0, t0), fmaxf(z1, t1));
}

struct MlpConsts {
    u64 a01, a23;              // layer-1 f-coeffs packed across hidden pairs
    u64 w2p01[4], w2p23[4];    // w2p01[i] = (W2[0][i], W2[1][i]); w2p23[i] = (W2[2][i], W2[3][i])
    u64 b2p01, b2p23;
    u64 w3p01, w3p23;
    u64 b3p;                   // (b3, 0)
    u64 k02;                   // (0.2, 0.2)
};

// full MLP for one element given f and its per-m layer-1 constants (packed across hidden dim)
__device__ __forceinline__ float mlp_eval(float f, u64 c01, u64 c23, const MlpConsts& C) {
    const u64 fs = pack2(f, f);
    const u64 h01 = leaky2(fma2(C.a01, fs, c01), C.k02);
    const u64 h23 = leaky2(fma2(C.a23, fs, c23), C.k02);
    float h0, h1, h2, h3;
    unpack2(h01, h0, h1); unpack2(h23, h2, h3);
    const u64 h0s = pack2(h0, h0), h1s = pack2(h1, h1),
              h2s = pack2(h2, h2), h3s = pack2(h3, h3);
    u64 z2a = fma2(h0s, C.w2p01[0],
              fma2(h1s, C.w2p01[1],
              fma2(h2s, C.w2p01[2],
              fma2(h3s, C.w2p01[3], C.b2p01))));
    u64 z2b = fma2(h0s, C.w2p23[0],
              fma2(h1s, C.w2p23[1],
              fma2(h2s, C.w2p23[2],
              fma2(h3s, C.w2p23[3], C.b2p23))));
    const u64 g01 = leaky2(z2a, C.k02);
    const u64 g23 = leaky2(z2b, C.k02);
    const u64 acc = fma2(C.w3p01, g01, fma2(C.w3p23, g23, C.b3p));
    float lo, hi; unpack2(acc, lo, hi);
    return lo + hi;
}

__global__ void __launch_bounds__(THREADS)
featuration_kernel(const float* __restrict__ xyz,   // [B,3,N]
                   const float* __restrict__ V,     // [B,M,3]
                   const float* __restrict__ W1,    // [4,4]
                   const float* __restrict__ b1,    // [4]
                   const float* __restrict__ W2,    // [4,4]
                   const float* __restrict__ b2,    // [4]
                   const float* __restrict__ W3,    // [1,4]
                   const float* __restrict__ b3,    // [1]
                   float* __restrict__ out)         // [B,N,M]
{
    __shared__ float4 Vs[M_DIM];   // (Vx,Vy,Vz,0) per m
    __shared__ float4 Cs[M_DIM];   // hoisted layer-1 constants per m

    const int b   = blockIdx.y;
    const int tid = threadIdx.x;

    // ---- per-CTA init: load V for this batch, precompute layer-1 constants ----
    // THREADS == 128 == M_DIM: every thread handles one m
    {
        const float vx = __ldg(&V[(b * M_DIM + tid) * 3 + 0]);
        const float vy = __ldg(&V[(b * M_DIM + tid) * 3 + 1]);
        const float vz = __ldg(&V[(b * M_DIM + tid) * 3 + 2]);
        Vs[tid] = make_float4(vx, vy, vz, 0.0f);
        float4 c;
        c.x = fmaf(__ldg(&W1[1]),  vx, fmaf(__ldg(&W1[2]),  vy, fmaf(__ldg(&W1[3]),  vz, __ldg(&b1[0]))));
        c.y = fmaf(__ldg(&W1[5]),  vx, fmaf(__ldg(&W1[6]),  vy, fmaf(__ldg(&W1[7]),  vz, __ldg(&b1[1]))));
        c.z = fmaf(__ldg(&W1[9]),  vx, fmaf(__ldg(&W1[10]), vy, fmaf(__ldg(&W1[11]), vz, __ldg(&b1[2]))));
        c.w = fmaf(__ldg(&W1[13]), vx, fmaf(__ldg(&W1[14]), vy, fmaf(__ldg(&W1[15]), vz, __ldg(&b1[3]))));
        Cs[tid] = c;
    }

    // ---- global weight constants, packed across the hidden axis ----
    MlpConsts C;
    C.a01 = pack2(__ldg(&W1[0]),  __ldg(&W1[4]));
    C.a23 = pack2(__ldg(&W1[8]),  __ldg(&W1[12]));
#pragma unroll
    for (int i = 0; i < 4; i++) {
        C.w2p01[i] = pack2(__ldg(&W2[i]),     __ldg(&W2[4 + i]));
        C.w2p23[i] = pack2(__ldg(&W2[8 + i]), __ldg(&W2[12 + i]));
    }
    C.b2p01 = pack2(__ldg(&b2[0]), __ldg(&b2[1]));
    C.b2p23 = pack2(__ldg(&b2[2]), __ldg(&b2[3]));
    C.w3p01 = pack2(__ldg(&W3[0]), __ldg(&W3[1]));
    C.w3p23 = pack2(__ldg(&W3[2]), __ldg(&W3[3]));
    C.b3p   = pack2(__ldg(&b3[0]), 0.0f);
    C.k02   = pack2(0.2f, 0.2f);

    __syncthreads();

    const int warp = tid >> 5;
    const int lane = tid & 31;

    // lane owns m = 4*lane .. 4*lane+3 ; negated V packed across m-pairs
    const float4 v0 = Vs[4 * lane + 0];
    const float4 v1 = Vs[4 * lane + 1];
    const float4 v2 = Vs[4 * lane + 2];
    const float4 v3 = Vs[4 * lane + 3];
    const u64 nvxA = pack2(-v0.x, -v1.x), nvyA = pack2(-v0.y, -v1.y), nvzA = pack2(-v0.z, -v1.z);
    const u64 nvxB = pack2(-v2.x, -v3.x), nvyB = pack2(-v2.y, -v3.y), nvzB = pack2(-v2.z, -v3.z);

    // layer-1 constants packed across hidden dim, per owned m
    const float4 cc0 = Cs[4 * lane + 0];
    const float4 cc1 = Cs[4 * lane + 1];
    const float4 cc2 = Cs[4 * lane + 2];
    const float4 cc3 = Cs[4 * lane + 3];
    const u64 c0_01 = pack2(cc0.x, cc0.y), c0_23 = pack2(cc0.z, cc0.w);
    const u64 c1_01 = pack2(cc1.x, cc1.y), c1_23 = pack2(cc1.z, cc1.w);
    const u64 c2_01 = pack2(cc2.x, cc2.y), c2_23 = pack2(cc2.z, cc2.w);
    const u64 c3_01 = pack2(cc3.x, cc3.y), c3_23 = pack2(cc3.z, cc3.w);

    const float* xb = xyz + (size_t)b * 3 * N_DIM;
    float* outb = out + (size_t)b * N_DIM * M_DIM;

    const int n_base = blockIdx.x * PTS_PER_CTA + warp * PTS_PER_WARP;

#pragma unroll
    for (int p = 0; p < PTS_PER_WARP; p++) {
        const int n = n_base + p;
        const float px = __ldg(&xb[n]);
        const float py = __ldg(&xb[N_DIM + n]);
        const float pz = __ldg(&xb[2 * N_DIM + n]);
        const u64 pxs = pack2(px, px), pys = pack2(py, py), pzs = pack2(pz, pz);

        // squared distances, packed across m-pairs
        u64 dxA = add2(pxs, nvxA), dyA = add2(pys, nvyA), dzA = add2(pzs, nvzA);
        u64 sA = fma2(dxA, dxA, fma2(dyA, dyA, mul2(dzA, dzA)));
        u64 dxB = add2(pxs, nvxB), dyB = add2(pys, nvyB), dzB = add2(pzs, nvzB);
        u64 sB = fma2(dxB, dxB, fma2(dyB, dyB, mul2(dzB, dzB)));
        float s0, s1, s2, s3;
        unpack2(sA, s0, s1); unpack2(sB, s2, s3);

        // butterfly on SQUARED distances (sqrt is monotone) so the four
        // per-element MUFU sqrts below overlap the SHFL chain
        float mns = fminf(fminf(s0, s1), fminf(s2, s3));
        float mxs = fmaxf(fmaxf(s0, s1), fmaxf(s2, s3));
#pragma unroll
        for (int off = 16; off > 0; off >>= 1) {
            mns = fminf(mns, __shfl_xor_sync(0xFFFFFFFFu, mns, off));
            mxs = fmaxf(mxs, __shfl_xor_sync(0xFFFFFFFFu, mxs, off));
        }

        const float d0 = sqrt_approx(s0);
        const float d1 = sqrt_approx(s1);
        const float d2 = sqrt_approx(s2);
        const float d3 = sqrt_approx(s3);

        const float mn = sqrt_approx(mns);
        const float mx = sqrt_approx(mxs);
        const float denom = mx - mn;
        const float inv = (denom > 0.0f) ? rcp_approx(denom) : 0.0f;
        const float nmninv = -mn * inv;

        float4 res;
        res.x = mlp_eval(fmaf(d0, inv, nmninv), c0_01, c0_23, C);
        res.y = mlp_eval(fmaf(d1, inv, nmninv), c1_01, c1_23, C);
        res.z = mlp_eval(fmaf(d2, inv, nmninv), c2_01, c2_23, C);
        res.w = mlp_eval(fmaf(d3, inv, nmninv), c3_01, c3_23, C);

        // coalesced: warp writes 128 contiguous floats
        reinterpret_cast<float4*>(outb + (size_t)n * M_DIM)[lane] = res;
    }
}

extern "C" void kernel_launch(void* const* d_in, const int* in_sizes, int n_in,
                              void* d_out, int out_size) {
    const float* xyz = (const float*)d_in[0];
    const float* V   = (const float*)d_in[1];
    const float* W1  = (const float*)d_in[2];
    const float* b1  = (const float*)d_in[3];
    const float* W2  = (const float*)d_in[4];
    const float* b2  = (const float*)d_in[5];
    const float* W3  = (const float*)d_in[6];
    const float* b3  = (const float*)d_in[7];
    float* out = (float*)d_out;

    dim3 grid(N_DIM / PTS_PER_CTA, B_DIM);  // (256, 8)
    featuration_kernel<<<grid, THREADS>>>(xyz, V, W1, b1, W2, b2, W3, b3, out);
}

// round 7
// speedup vs baseline: 1.0629x; 1.0014x over previous
#include <cuda_runtime.h>

#ifndef B_DIM
#define B_DIM 8
#define N_DIM 8192
#define M_DIM 128
#endif

constexpr int WARPS_PER_CTA = 4;
constexpr int GROUP         = 4;   // points processed with interleaved chains
constexpr int GROUPS_PER_WARP = 2; // 8 points per warp total
constexpr int PTS_PER_WARP  = GROUP * GROUPS_PER_WARP;       // 8
constexpr int PTS_PER_CTA   = WARPS_PER_CTA * PTS_PER_WARP;  // 32
constexpr int THREADS       = WARPS_PER_CTA * 32;            // 128

typedef unsigned long long u64;

// ---------- packed f32x2 helpers (Blackwell) ----------
__device__ __forceinline__ u64 pack2(float lo, float hi) {
    u64 r; asm("mov.b64 %0, {%1,%2};" : "=l"(r) : "f"(lo), "f"(hi)); return r;
}
__device__ __forceinline__ void unpack2(u64 v, float& lo, float& hi) {
    asm("mov.b64 {%0,%1}, %2;" : "=f"(lo), "=f"(hi) : "l"(v));
}
__device__ __forceinline__ u64 fma2(u64 a, u64 b, u64 c) {
    u64 d; asm("fma.rn.f32x2 %0, %1, %2, %3;" : "=l"(d) : "l"(a), "l"(b), "l"(c)); return d;
}
__device__ __forceinline__ u64 mul2(u64 a, u64 b) {
    u64 d; asm("mul.rn.f32x2 %0, %1, %2;" : "=l"(d) : "l"(a), "l"(b)); return d;
}
__device__ __forceinline__ u64 add2(u64 a, u64 b) {
    u64 d; asm("add.rn.f32x2 %0, %1, %2;" : "=l"(d) : "l"(a), "l"(b)); return d;
}
__device__ __forceinline__ float sqrt_approx(float x) {
    float r; asm("sqrt.approx.f32 %0, %1;" : "=f"(r) : "f"(x)); return r;
}
__device__ __forceinline__ float rcp_approx(float x) {
    float r; asm("rcp.approx.f32 %0, %1;" : "=f"(r) : "f"(x)); return r;
}

// packed leaky: max(z, 0.2z) per component
__device__ __forceinline__ u64 leaky2(u64 z, u64 k02) {
    u64 t = mul2(z, k02);
    float z0, z1, t0, t1;
    unpack2(z, z0, z1); unpack2(t, t0, t1);
    return pack2(fmaxf(z0, t0), fmaxf(z1, t1));
}

struct MlpConsts {
    u64 a01, a23;
    u64 w2p01[4], w2p23[4];
    u64 b2p01, b2p23;
    u64 w3p01, w3p23;
    u64 b3p;
    u64 k02;
};

__device__ __forceinline__ float mlp_eval(float f, u64 c01, u64 c23, const MlpConsts& C) {
    const u64 fs = pack2(f, f);
    const u64 h01 = leaky2(fma2(C.a01, fs, c01), C.k02);
    const u64 h23 = leaky2(fma2(C.a23, fs, c23), C.k02);
    float h0, h1, h2, h3;
    unpack2(h01, h0, h1); unpack2(h23, h2, h3);
    const u64 h0s = pack2(h0, h0), h1s = pack2(h1, h1),
              h2s = pack2(h2, h2), h3s = pack2(h3, h3);
    u64 z2a = fma2(h0s, C.w2p01[0],
              fma2(h1s, C.w2p01[1],
              fma2(h2s, C.w2p01[2],
              fma2(h3s, C.w2p01[3], C.b2p01))));
    u64 z2b = fma2(h0s, C.w2p23[0],
              fma2(h1s, C.w2p23[1],
              fma2(h2s, C.w2p23[2],
              fma2(h3s, C.w2p23[3], C.b2p23))));
    const u64 g01 = leaky2(z2a, C.k02);
    const u64 g23 = leaky2(z2b, C.k02);
    const u64 acc = fma2(C.w3p01, g01, fma2(C.w3p23, g23, C.b3p));
    float lo, hi; unpack2(acc, lo, hi);
    return lo + hi;
}

__global__ void __launch_bounds__(THREADS)
featuration_kernel(const float* __restrict__ xyz,   // [B,3,N]
                   const float* __restrict__ V,     // [B,M,3]
                   const float* __restrict__ W1,    // [4,4]
                   const float* __restrict__ b1,    // [4]
                   const float* __restrict__ W2,    // [4,4]
                   const float* __restrict__ b2,    // [4]
                   const float* __restrict__ W3,    // [1,4]
                   const float* __restrict__ b3,    // [1]
                   float* __restrict__ out)         // [B,N,M]
{
    __shared__ float4 Vs[M_DIM];
    __shared__ float4 Cs[M_DIM];

    const int b   = blockIdx.y;
    const int tid = threadIdx.x;

    // THREADS == 128 == M_DIM: every thread handles one m
    {
        const float vx = __ldg(&V[(b * M_DIM + tid) * 3 + 0]);
        const float vy = __ldg(&V[(b * M_DIM + tid) * 3 + 1]);
        const float vz = __ldg(&V[(b * M_DIM + tid) * 3 + 2]);
        Vs[tid] = make_float4(vx, vy, vz, 0.0f);
        float4 c;
        c.x = fmaf(__ldg(&W1[1]),  vx, fmaf(__ldg(&W1[2]),  vy, fmaf(__ldg(&W1[3]),  vz, __ldg(&b1[0]))));
        c.y = fmaf(__ldg(&W1[5]),  vx, fmaf(__ldg(&W1[6]),  vy, fmaf(__ldg(&W1[7]),  vz, __ldg(&b1[1]))));
        c.z = fmaf(__ldg(&W1[9]),  vx, fmaf(__ldg(&W1[10]), vy, fmaf(__ldg(&W1[11]), vz, __ldg(&b1[2]))));
        c.w = fmaf(__ldg(&W1[13]), vx, fmaf(__ldg(&W1[14]), vy, fmaf(__ldg(&W1[15]), vz, __ldg(&b1[3]))));
        Cs[tid] = c;
    }

    MlpConsts C;
    C.a01 = pack2(__ldg(&W1[0]),  __ldg(&W1[4]));
    C.a23 = pack2(__ldg(&W1[8]),  __ldg(&W1[12]));
#pragma unroll
    for (int i = 0; i < 4; i++) {
        C.w2p01[i] = pack2(__ldg(&W2[i]),     __ldg(&W2[4 + i]));
        C.w2p23[i] = pack2(__ldg(&W2[8 + i]), __ldg(&W2[12 + i]));
    }
    C.b2p01 = pack2(__ldg(&b2[0]), __ldg(&b2[1]));
    C.b2p23 = pack2(__ldg(&b2[2]), __ldg(&b2[3]));
    C.w3p01 = pack2(__ldg(&W3[0]), __ldg(&W3[1]));
    C.w3p23 = pack2(__ldg(&W3[2]), __ldg(&W3[3]));
    C.b3p   = pack2(__ldg(&b3[0]), 0.0f);
    C.k02   = pack2(0.2f, 0.2f);

    __syncthreads();

    const int warp = tid >> 5;
    const int lane = tid & 31;

    const float4 v0 = Vs[4 * lane + 0];
    const float4 v1 = Vs[4 * lane + 1];
    const float4 v2 = Vs[4 * lane + 2];
    const float4 v3 = Vs[4 * lane + 3];
    const u64 nvxA = pack2(-v0.x, -v1.x), nvyA = pack2(-v0.y, -v1.y), nvzA = pack2(-v0.z, -v1.z);
    const u64 nvxB = pack2(-v2.x, -v3.x), nvyB = pack2(-v2.y, -v3.y), nvzB = pack2(-v2.z, -v3.z);

    const float4 cc0 = Cs[4 * lane + 0];
    const float4 cc1 = Cs[4 * lane + 1];
    const float4 cc2 = Cs[4 * lane + 2];
    const float4 cc3 = Cs[4 * lane + 3];
    const u64 c0_01 = pack2(cc0.x, cc0.y), c0_23 = pack2(cc0.z, cc0.w);
    const u64 c1_01 = pack2(cc1.x, cc1.y), c1_23 = pack2(cc1.z, cc1.w);
    const u64 c2_01 = pack2(cc2.x, cc2.y), c2_23 = pack2(cc2.z, cc2.w);
    const u64 c3_01 = pack2(cc3.x, cc3.y), c3_23 = pack2(cc3.z, cc3.w);

    const float* xb = xyz + (size_t)b * 3 * N_DIM;
    float* outb = out + (size_t)b * N_DIM * M_DIM;

    const int n_base = blockIdx.x * PTS_PER_CTA + warp * PTS_PER_WARP;

#pragma unroll
    for (int g = 0; g < GROUPS_PER_WARP; g++) {
        const int n0 = n_base + g * GROUP;

        // ---- Phase A: squared distances + local folds for GROUP points ----
        float4 sv[GROUP];
        float mns[GROUP], mxs[GROUP];
#pragma unroll
        for (int q = 0; q < GROUP; q++) {
            const int n = n0 + q;
            const float px = __ldg(&xb[n]);
            const float py = __ldg(&xb[N_DIM + n]);
            const float pz = __ldg(&xb[2 * N_DIM + n]);
            const u64 pxs = pack2(px, px), pys = pack2(py, py), pzs = pack2(pz, pz);

            const u64 dxA = add2(pxs, nvxA), dyA = add2(pys, nvyA), dzA = add2(pzs, nvzA);
            const u64 sA  = fma2(dxA, dxA, fma2(dyA, dyA, mul2(dzA, dzA)));
            const u64 dxB = add2(pxs, nvxB), dyB = add2(pys, nvyB), dzB = add2(pzs, nvzB);
            const u64 sB  = fma2(dxB, dxB, fma2(dyB, dyB, mul2(dzB, dzB)));
            float s0, s1, s2, s3;
            unpack2(sA, s0, s1); unpack2(sB, s2, s3);
            sv[q] = make_float4(s0, s1, s2, s3);
            mns[q] = fminf(fminf(s0, s1), fminf(s2, s3));
            mxs[q] = fmaxf(fmaxf(s0, s1), fmaxf(s2, s3));
        }

        // ---- Phase B: GROUP interleaved butterflies (level outer, point inner) ----
#pragma unroll
        for (int off = 16; off > 0; off >>= 1) {
#pragma unroll
            for (int q = 0; q < GROUP; q++) {
                mns[q] = fminf(mns[q], __shfl_xor_sync(0xFFFFFFFFu, mns[q], off));
                mxs[q] = fmaxf(mxs[q], __shfl_xor_sync(0xFFFFFFFFu, mxs[q], off));
            }
        }

        // ---- Phase C: normalize + MLP + store per point ----
#pragma unroll
        for (int q = 0; q < GROUP; q++) {
            const int n = n0 + q;
            const float d0 = sqrt_approx(sv[q].x);
            const float d1 = sqrt_approx(sv[q].y);
            const float d2 = sqrt_approx(sv[q].z);
            const float d3 = sqrt_approx(sv[q].w);
            const float mn = sqrt_approx(mns[q]);
            const float mx = sqrt_approx(mxs[q]);
            const float denom = mx - mn;
            const float inv = (denom > 0.0f) ? rcp_approx(denom) : 0.0f;
            const float nmninv = -mn * inv;

            float4 res;
            res.x = mlp_eval(fmaf(d0, inv, nmninv), c0_01, c0_23, C);
            res.y = mlp_eval(fmaf(d1, inv, nmninv), c1_01, c1_23, C);
            res.z = mlp_eval(fmaf(d2, inv, nmninv), c2_01, c2_23, C);
            res.w = mlp_eval(fmaf(d3, inv, nmninv), c3_01, c3_23, C);

            reinterpret_cast<float4*>(outb + (size_t)n * M_DIM)[lane] = res;
        }
    }
}

extern "C" void kernel_launch(void* const* d_in, const int* in_sizes, int n_in,
                              void* d_out, int out_size) {
    const float* xyz = (const float*)d_in[0];
    const float* V   = (const float*)d_in[1];
    const float* W1  = (const float*)d_in[2];
    const float* b1  = (const float*)d_in[3];
    const float* W2  = (const float*)d_in[4];
    const float* b2  = (const float*)d_in[5];
    const float* W3  = (const float*)d_in[6];
    const float* b3  = (const float*)d_in[7];
    float* out = (float*)d_out;

    dim3 grid(N_DIM / PTS_PER_CTA, B_DIM);  // (256, 8)
    featuration_kernel<<<grid, THREADS>>>(xyz, V, W1, b1, W2, b2, W3, b3, out);
}